// round 13
// baseline (speedup 1.0000x reference)
#include <cuda_runtime.h>
#include <cuda_fp16.h>
#include <cstdint>

#define NR 8192
#define MC 8192
#define DD 64

// ---------------- device-global staging (no allocation allowed) ----------------
__device__ __align__(16) __half g_ah[NR * DD];   // A: fp16
__device__ __align__(16) __half g_bh[MC * DD];   // B: fp16
// stats: x = |p|^2 (fp32) ; y = SQUARED reciprocal term
__device__ float2 g_apa[NR];
__device__ float2 g_bq[MC];

// ---------------- helpers ----------------
__device__ __forceinline__ float fast_sqrt(float x) {
    float r; asm("sqrt.approx.f32 %0, %1;" : "=f"(r) : "f"(x)); return r;
}
__device__ __forceinline__ uint32_t smem_u32(const void* p) {
    uint32_t a;
    asm("{ .reg .u64 t; cvta.to.shared.u64 t, %1; cvt.u32.u64 %0, t; }" : "=r"(a) : "l"(p));
    return a;
}
#define CP_ASYNC16(dst, src) \
    asm volatile("cp.async.cg.shared.global [%0], [%1], 16;" :: "r"(dst), "l"(src) : "memory")
#define CP_COMMIT() asm volatile("cp.async.commit_group;" ::: "memory")
#define CP_WAIT0()  asm volatile("cp.async.wait_group 0;" ::: "memory")

#define LDSM4(R, a) \
    asm volatile("ldmatrix.sync.aligned.m8n8.x4.shared.b16 {%0,%1,%2,%3}, [%4];" \
        : "=r"((R)[0]), "=r"((R)[1]), "=r"((R)[2]), "=r"((R)[3]) : "r"(a))

#define MMA16816(d, a, b0, b1) \
    asm volatile("mma.sync.aligned.m16n8k16.row.col.f32.f16.f16.f32 " \
        "{%0,%1,%2,%3}, {%4,%5,%6,%7}, {%8,%9}, {%0,%1,%2,%3};" \
        : "+f"((d)[0]), "+f"((d)[1]), "+f"((d)[2]), "+f"((d)[3]) \
        : "r"((a)[0]), "r"((a)[1]), "r"((a)[2]), "r"((a)[3]), "r"(b0), "r"(b1))

// ---------------- prep: norms + SQUARED reciprocal terms + fp16 convert ----------------
__global__ void poincare_prep_kernel(const float* __restrict__ a,
                                     const float* __restrict__ b) {
    int warp = (blockIdx.x * blockDim.x + threadIdx.x) >> 5;
    int lane = threadIdx.x & 31;
    bool isA = warp < NR;
    int r = isA ? warp : warp - NR;
    const float* row = (isA ? a : b) + (size_t)r * DD;

    float v0 = row[lane], v1 = row[lane + 32];
    __half* dst = (isA ? g_ah : g_bh) + (size_t)r * DD;
    dst[lane]      = __float2half_rn(v0);
    dst[lane + 32] = __float2half_rn(v1);

    float s = fmaf(v0, v0, v1 * v1);
    #pragma unroll
    for (int o = 16; o > 0; o >>= 1) s += __shfl_xor_sync(0xffffffffu, s, o);
    if (lane == 0) {
        if (isA) {
            float t = 2.0f / (1.0f - s);
            g_apa[r] = make_float2(s, t * t);
        } else {
            float t = 1.0f / (1.0f - s);
            g_bq[r] = make_float2(s, t * t);
        }
    }
}

// ---------------- main: warp-decoupled single-pass fp16 HMMA + fused epilogue ----------------
// CTA tile 64(M) x 128(N); 8 warps = 2(M) x 4(N), warp tile 32x32; 3 CTAs/SM.
// NO __syncthreads: each warp cp.asyncs exactly the A/B slice it reads
// (A duplicated by 4 warps, B by 2 — benign same-value races), waits its own
// group, __syncwarp, and free-runs. 24 independent warps/SM stagger phases.
#define PITCH 144
#define A_TILE_BYTES (64 * PITCH)     // 9216
#define B_TILE_BYTES (128 * PITCH)    // 18432
#define SMEM_TOTAL (A_TILE_BYTES + B_TILE_BYTES)   // 27648

__global__ void __launch_bounds__(256, 3)
poincare_hmma_kernel(float* __restrict__ out) {
    extern __shared__ char smem[];
    const uint32_t uA = smem_u32(smem);
    const uint32_t uB = uA + A_TILE_BYTES;

    const int tid = threadIdx.x;
    const int lane = tid & 31;
    const int wid = tid >> 5;
    const int wm = wid >> 2;       // 0..1
    const int wn = wid & 3;        // 0..3

    const int row0 = blockIdx.y * 64;
    const int col0 = blockIdx.x * 128;

    // ---- per-warp staging: load exactly the rows this warp will LDSM ----
    // A rows [wm*32, wm*32+32), B rows [wn*32, wn*32+32); 8 chunks of 16B per row.
    #pragma unroll
    for (int i = 0; i < 8; i++) {
        int chunk = lane + 32 * i;          // 0..255
        int r = chunk >> 3;                 // 0..31
        int kc = chunk & 7;
        int ar = wm * 32 + r;
        int br = wn * 32 + r;
        CP_ASYNC16(uA + (uint32_t)(ar * PITCH + kc * 16),
                   g_ah + (size_t)(row0 + ar) * DD + kc * 8);
        CP_ASYNC16(uB + (uint32_t)(br * PITCH + kc * 16),
                   g_bh + (size_t)(col0 + br) * DD + kc * 8);
    }
    CP_COMMIT();

    // ---- hoisted epilogue stats (global loads overlap cp.async) ----
    const int er = row0 + wm * 32 + (lane >> 2);
    const int ec = col0 + wn * 32 + 2 * (lane & 3);
    float2 rs[2][2];
    float2 cs[4][2];
    #pragma unroll
    for (int mf = 0; mf < 2; mf++) {
        rs[mf][0] = __ldg(&g_apa[er + mf * 16]);
        rs[mf][1] = __ldg(&g_apa[er + mf * 16 + 8]);
    }
    #pragma unroll
    for (int nf = 0; nf < 4; nf++) {
        cs[nf][0] = __ldg(&g_bq[ec + nf * 8]);
        cs[nf][1] = __ldg(&g_bq[ec + nf * 8 + 1]);
    }

    float acc[2][4][4];
    #pragma unroll
    for (int i = 0; i < 2; i++)
        #pragma unroll
        for (int j = 0; j < 4; j++)
            #pragma unroll
            for (int q = 0; q < 4; q++) acc[i][j][q] = 0.0f;

    const uint32_t a_row  = (uint32_t)(wm * 32 + (lane & 15));
    const uint32_t a_koff = (uint32_t)((lane >> 4) * 16);
    const uint32_t b_row  = (uint32_t)(wn * 32 + ((lane & 16) >> 1) + (lane & 7));
    const uint32_t b_koff = (uint32_t)(((lane >> 3) & 1) * 16);

    CP_WAIT0();
    __syncwarp();     // own-warp cp.async writes visible to all lanes

    #pragma unroll
    for (int ks = 0; ks < 4; ks++) {
        const uint32_t kb = (uint32_t)(ks * 32);
        uint32_t Ah[2][4];
        #pragma unroll
        for (int mf = 0; mf < 2; mf++) {
            uint32_t off = (a_row + mf * 16) * PITCH + kb + a_koff;
            LDSM4(Ah[mf], uA + off);
        }
        uint32_t Bh[2][4];
        #pragma unroll
        for (int nh = 0; nh < 2; nh++) {
            uint32_t off = (b_row + nh * 16) * PITCH + kb + b_koff;
            LDSM4(Bh[nh], uB + off);
        }
        #pragma unroll
        for (int nf = 0; nf < 4; nf++) {
            uint32_t b0 = Bh[nf >> 1][(nf & 1) * 2], b1 = Bh[nf >> 1][(nf & 1) * 2 + 1];
            #pragma unroll
            for (int mf = 0; mf < 2; mf++)
                MMA16816(acc[mf][nf], Ah[mf], b0, b1);
        }
    }

    // ---- fused Poincare epilogue (z-form, squared stats) ----
    #pragma unroll
    for (int mf = 0; mf < 2; mf++) {
        #pragma unroll
        for (int nf = 0; nf < 4; nf++) {
            float res[4];
            #pragma unroll
            for (int q = 0; q < 4; q++) {
                float2 ra = rs[mf][q >> 1];
                float2 cb = cs[nf][q & 1];
                float sq = fmaf(-2.0f, acc[mf][nf][q], ra.x + cb.x);
                sq = fmaxf(sq, 0.0f);
                float z  = (sq * ra.y) * cb.y;
                float y  = fast_sqrt(z);
                float tt = fmaf(2.0f, y, z);
                res[q] = __logf(1.0f + y + fast_sqrt(tt));
            }
            size_t r0 = (size_t)(er + mf * 16) * MC + (ec + nf * 8);
            *reinterpret_cast<float2*>(out + r0)          = make_float2(res[0], res[1]);
            *reinterpret_cast<float2*>(out + r0 + 8 * MC) = make_float2(res[2], res[3]);
        }
    }
}

extern "C" void kernel_launch(void* const* d_in, const int* in_sizes, int n_in,
                              void* d_out, int out_size) {
    const float* a = (const float*)d_in[0];
    const float* b = (const float*)d_in[1];
    float* out = (float*)d_out;

    cudaFuncSetAttribute(poincare_hmma_kernel,
                         cudaFuncAttributeMaxDynamicSharedMemorySize, SMEM_TOTAL);

    poincare_prep_kernel<<<(NR + MC) / 8, 256>>>(a, b);
    dim3 grid(MC / 128, NR / 64);
    poincare_hmma_kernel<<<grid, 256, SMEM_TOTAL>>>(out);
}

// round 14
// speedup vs baseline: 1.1231x; 1.1231x over previous
#include <cuda_runtime.h>
#include <cuda_fp16.h>
#include <cstdint>

#define NR 8192
#define MC 8192
#define DD 64

// ---------------- device-global staging (no allocation allowed) ----------------
__device__ __align__(16) __half g_ah[NR * DD];   // A: fp16
__device__ __align__(16) __half g_bh[MC * DD];   // B: fp16
// stats: x = |p|^2 (fp32) ; y = SQUARED reciprocal term
__device__ float2 g_apa[NR];
__device__ float2 g_bq[MC];

// ---------------- helpers ----------------
__device__ __forceinline__ float fast_sqrt(float x) {
    float r; asm("sqrt.approx.f32 %0, %1;" : "=f"(r) : "f"(x)); return r;
}
__device__ __forceinline__ uint32_t smem_u32(const void* p) {
    uint32_t a;
    asm("{ .reg .u64 t; cvta.to.shared.u64 t, %1; cvt.u32.u64 %0, t; }" : "=r"(a) : "l"(p));
    return a;
}
#define CP_ASYNC16(dst, src) \
    asm volatile("cp.async.cg.shared.global [%0], [%1], 16;" :: "r"(dst), "l"(src) : "memory")
#define CP_COMMIT() asm volatile("cp.async.commit_group;" ::: "memory")
#define CP_WAIT0()  asm volatile("cp.async.wait_group 0;" ::: "memory")

#define LDSM4(R, a) \
    asm volatile("ldmatrix.sync.aligned.m8n8.x4.shared.b16 {%0,%1,%2,%3}, [%4];" \
        : "=r"((R)[0]), "=r"((R)[1]), "=r"((R)[2]), "=r"((R)[3]) : "r"(a))

#define MMA16816(d, a, b0, b1) \
    asm volatile("mma.sync.aligned.m16n8k16.row.col.f32.f16.f16.f32 " \
        "{%0,%1,%2,%3}, {%4,%5,%6,%7}, {%8,%9}, {%0,%1,%2,%3};" \
        : "+f"((d)[0]), "+f"((d)[1]), "+f"((d)[2]), "+f"((d)[3]) \
        : "r"((a)[0]), "r"((a)[1]), "r"((a)[2]), "r"((a)[3]), "r"(b0), "r"(b1))

// ---------------- prep: norms + SQUARED reciprocal terms + fp16 convert ----------------
__global__ void poincare_prep_kernel(const float* __restrict__ a,
                                     const float* __restrict__ b) {
    int warp = (blockIdx.x * blockDim.x + threadIdx.x) >> 5;
    int lane = threadIdx.x & 31;
    bool isA = warp < NR;
    int r = isA ? warp : warp - NR;
    const float* row = (isA ? a : b) + (size_t)r * DD;

    float v0 = row[lane], v1 = row[lane + 32];
    __half* dst = (isA ? g_ah : g_bh) + (size_t)r * DD;
    dst[lane]      = __float2half_rn(v0);
    dst[lane + 32] = __float2half_rn(v1);

    float s = fmaf(v0, v0, v1 * v1);
    #pragma unroll
    for (int o = 16; o > 0; o >>= 1) s += __shfl_xor_sync(0xffffffffu, s, o);
    if (lane == 0) {
        if (isA) {
            float t = 2.0f / (1.0f - s);
            g_apa[r] = make_float2(s, t * t);
        } else {
            float t = 1.0f / (1.0f - s);
            g_bq[r] = make_float2(s, t * t);
        }
    }
}

// ---------------- main: single-pass fp16 HMMA GEMM + fused Poincare epilogue ----------------
// CTA tile 64(M) x 128(N); 8 warps = 2(M) x 4(N), warp tile 32x32.
// Register diet (stats loaded inline in epilogue) -> 64 regs -> 4 CTAs/SM.
#define PITCH 144
#define A_TILE_BYTES (64 * PITCH)     // 9216
#define B_TILE_BYTES (128 * PITCH)    // 18432
#define SMEM_TOTAL (A_TILE_BYTES + B_TILE_BYTES)   // 27648 -> 4 CTAs/SM fits

__global__ void __launch_bounds__(256, 4)
poincare_hmma_kernel(float* __restrict__ out) {
    extern __shared__ char smem[];
    const uint32_t uA = smem_u32(smem);
    const uint32_t uB = uA + A_TILE_BYTES;

    const int tid = threadIdx.x;
    const int lane = tid & 31;
    const int wid = tid >> 5;
    const int wm = wid >> 2;
    const int wn = wid & 3;

    const int row0 = blockIdx.y * 64;
    const int col0 = blockIdx.x * 128;

    // ---- stage tiles via cp.async (cooperative, R12 layout) ----
    #pragma unroll
    for (int t = 0; t < 2; t++) {
        int chunk = tid + 256 * t;          // 0..511
        int r = chunk >> 3;
        int kc = chunk & 7;
        CP_ASYNC16(uA + (uint32_t)(r * PITCH + kc * 16),
                   g_ah + (size_t)(row0 + r) * DD + kc * 8);
    }
    #pragma unroll
    for (int t = 0; t < 4; t++) {
        int chunk = tid + 256 * t;          // 0..1023
        int r = chunk >> 3;
        int kc = chunk & 7;
        CP_ASYNC16(uB + (uint32_t)(r * PITCH + kc * 16),
                   g_bh + (size_t)(col0 + r) * DD + kc * 8);
    }
    CP_COMMIT();
    CP_WAIT0();
    __syncthreads();

    float acc[2][4][4];
    #pragma unroll
    for (int i = 0; i < 2; i++)
        #pragma unroll
        for (int j = 0; j < 4; j++)
            #pragma unroll
            for (int q = 0; q < 4; q++) acc[i][j][q] = 0.0f;

    const uint32_t a_row  = (uint32_t)(wm * 32 + (lane & 15));
    const uint32_t a_koff = (uint32_t)((lane >> 4) * 16);
    const uint32_t b_row  = (uint32_t)(wn * 32 + ((lane & 16) >> 1) + (lane & 7));
    const uint32_t b_koff = (uint32_t)(((lane >> 3) & 1) * 16);

    #pragma unroll
    for (int ks = 0; ks < 4; ks++) {
        const uint32_t kb = (uint32_t)(ks * 32);
        uint32_t Ah[2][4];
        #pragma unroll
        for (int mf = 0; mf < 2; mf++) {
            uint32_t off = (a_row + mf * 16) * PITCH + kb + a_koff;
            LDSM4(Ah[mf], uA + off);
        }
        uint32_t Bh[2][4];
        #pragma unroll
        for (int nh = 0; nh < 2; nh++) {
            uint32_t off = (b_row + nh * 16) * PITCH + kb + b_koff;
            LDSM4(Bh[nh], uB + off);
        }
        #pragma unroll
        for (int nf = 0; nf < 4; nf++) {
            uint32_t b0 = Bh[nf >> 1][(nf & 1) * 2], b1 = Bh[nf >> 1][(nf & 1) * 2 + 1];
            #pragma unroll
            for (int mf = 0; mf < 2; mf++)
                MMA16816(acc[mf][nf], Ah[mf], b0, b1);
        }
    }

    // ---- fused Poincare epilogue; stats loaded inline (frees regs during MMA) ----
    const int er = row0 + wm * 32 + (lane >> 2);
    const int ec = col0 + wn * 32 + 2 * (lane & 3);

    #pragma unroll
    for (int mf = 0; mf < 2; mf++) {
        const float2 ra0 = __ldg(&g_apa[er + mf * 16]);
        const float2 ra1 = __ldg(&g_apa[er + mf * 16 + 8]);
        #pragma unroll
        for (int nf = 0; nf < 4; nf++) {
            const float2 cb0 = __ldg(&g_bq[ec + nf * 8]);
            const float2 cb1 = __ldg(&g_bq[ec + nf * 8 + 1]);
            float res[4];
            #pragma unroll
            for (int q = 0; q < 4; q++) {
                const float2 ra = (q >> 1) ? ra1 : ra0;
                const float2 cb = (q & 1) ? cb1 : cb0;
                float sq = fmaf(-2.0f, acc[mf][nf][q], ra.x + cb.x);
                sq = fmaxf(sq, 0.0f);
                float z  = (sq * ra.y) * cb.y;
                float y  = fast_sqrt(z);
                float tt = fmaf(2.0f, y, z);
                res[q] = __logf(1.0f + y + fast_sqrt(tt));
            }
            size_t r0 = (size_t)(er + mf * 16) * MC + (ec + nf * 8);
            *reinterpret_cast<float2*>(out + r0)          = make_float2(res[0], res[1]);
            *reinterpret_cast<float2*>(out + r0 + 8 * MC) = make_float2(res[2], res[3]);
        }
    }
}

extern "C" void kernel_launch(void* const* d_in, const int* in_sizes, int n_in,
                              void* d_out, int out_size) {
    const float* a = (const float*)d_in[0];
    const float* b = (const float*)d_in[1];
    float* out = (float*)d_out;

    cudaFuncSetAttribute(poincare_hmma_kernel,
                         cudaFuncAttributeMaxDynamicSharedMemorySize, SMEM_TOTAL);

    poincare_prep_kernel<<<(NR + MC) / 8, 256>>>(a, b);
    dim3 grid(MC / 128, NR / 64);
    poincare_hmma_kernel<<<grid, 256, SMEM_TOTAL>>>(out);
}